// round 2
// baseline (speedup 1.0000x reference)
#include <cuda_runtime.h>
#include <math.h>

#define MAXN 200000
#define MAXE 3200000

// ---------------- scratch (device globals: no allocation allowed) ----------------
__device__ __align__(16) float g_agg1[(size_t)MAXN * 24];   // 21 used, padded to 24 for 16B rows
__device__ __align__(16) float g_z1[(size_t)MAXN * 64];
__device__ __align__(16) float g_h[(size_t)MAXN * 64];
__device__ __align__(16) float g_agg2[(size_t)MAXN * 64];
__device__ __align__(16) float g_z2[(size_t)MAXN * 128];
__device__ float g_stats[384];                // [0..127]: bn1 sum/ss, [128..383]: bn2 sum/ss
__device__ float g_bn1[128];                  // scale[64], shift[64]
__device__ float g_bn2[256];                  // scale[128], shift[128]
__device__ __align__(16) float g_pooled[64 * 128];

__device__ __forceinline__ float gelu_(float x) {
    return 0.5f * x * (1.0f + erff(x * 0.7071067811865476f));
}

__device__ __forceinline__ void red4(float* p, float a, float b, float c, float d) {
    asm volatile("red.global.add.v4.f32 [%0], {%1,%2,%3,%4};"
                 :: "l"(p), "f"(a), "f"(b), "f"(c), "f"(d) : "memory");
}

// ---------------- kernel 1: edge MLP + scatter msg into agg1 ----------------
// msg = [nodes[src](5), e_emb(16)]  -> agg1[dst] (stride 24)
__global__ void __launch_bounds__(256) k_edge1(
    const int* __restrict__ ei, const float* __restrict__ ef,
    const float* __restrict__ nodes,
    const float* __restrict__ We1, const float* __restrict__ be1,
    const float* __restrict__ We2, const float* __restrict__ be2,
    float* __restrict__ agg1, int E)
{
    __shared__ float sWe1[48], sbe1[16], sWe2[256], sbe2[16];
    int t = threadIdx.x;
    if (t < 48)  sWe1[t] = We1[t];
    if (t < 16)  sbe1[t] = be1[t];
    if (t < 256) sWe2[t] = We2[t];
    if (t >= 48 && t < 64) sbe2[t - 48] = be2[t - 48];
    __syncthreads();

    int e = blockIdx.x * 256 + t;
    if (e >= E) return;

    float f0 = ef[3 * e], f1 = ef[3 * e + 1], f2 = ef[3 * e + 2];
    float emb[16];
#pragma unroll
    for (int j = 0; j < 16; j++) {
        float v = sbe1[j] + f0 * sWe1[j] + f1 * sWe1[16 + j] + f2 * sWe1[32 + j];
        emb[j] = gelu_(v);
    }
    float out[16];
#pragma unroll
    for (int j = 0; j < 16; j++) {
        float a = sbe2[j];
#pragma unroll
        for (int k = 0; k < 16; k++) a += emb[k] * sWe2[k * 16 + j];
        out[j] = a;
    }
    int src = ei[e], dst = ei[E + e];
    const float* np = nodes + (size_t)src * 5;
    float n0 = np[0], n1 = np[1], n2 = np[2], n3 = np[3], n4 = np[4];

    float* ap = agg1 + (size_t)dst * 24;
    red4(ap + 0,  n0, n1, n2, n3);
    red4(ap + 4,  n4, out[0], out[1], out[2]);
    red4(ap + 8,  out[3], out[4], out[5], out[6]);
    red4(ap + 12, out[7], out[8], out[9], out[10]);
    red4(ap + 16, out[11], out[12], out[13], out[14]);
    atomicAdd(ap + 20, out[15]);
}

// ---------------- kernel 2: z1 = ((1+eps1)*ego + agg1) @ W1a + b1a ----------------
__global__ void __launch_bounds__(128) k_node1(
    const float* __restrict__ nodes, const float* __restrict__ agg1,
    const float* __restrict__ Wego, const float* __restrict__ W1a,
    const float* __restrict__ b1a, const float* __restrict__ eps1,
    float* __restrict__ z1, int N)
{
    __shared__ __align__(16) float sW[21 * 64];
    __shared__ float sWe[108], sb[64];
    int t = threadIdx.x;
    if (t < 105) sWe[t] = Wego[t];
    for (int i = t; i < 1344; i += 128) sW[i] = W1a[i];
    if (t < 64) sb[t] = b1a[t];
    __syncthreads();

    int n = blockIdx.x * 128 + t;
    if (n >= N) return;

    float e1 = 1.0f + eps1[0];
    const float* nr = nodes + (size_t)n * 5;
    float x0 = nr[0], x1 = nr[1], x2 = nr[2], x3 = nr[3], x4 = nr[4];
    const float* ar = agg1 + (size_t)n * 24;

    float u[21];
#pragma unroll
    for (int c = 0; c < 21; c++) {
        float ego = x0 * sWe[c] + x1 * sWe[21 + c] + x2 * sWe[42 + c]
                  + x3 * sWe[63 + c] + x4 * sWe[84 + c];
        u[c] = e1 * ego + ar[c];
    }
    float acc[64];
#pragma unroll
    for (int c = 0; c < 64; c++) acc[c] = sb[c];
#pragma unroll 3
    for (int k = 0; k < 21; k++) {
        float uk = u[k];
        const float4* wr = (const float4*)(sW + k * 64);
#pragma unroll
        for (int c4 = 0; c4 < 16; c4++) {
            float4 w = wr[c4];
            acc[4 * c4 + 0] += uk * w.x; acc[4 * c4 + 1] += uk * w.y;
            acc[4 * c4 + 2] += uk * w.z; acc[4 * c4 + 3] += uk * w.w;
        }
    }
    float4* zo = (float4*)(z1 + (size_t)n * 64);
#pragma unroll
    for (int c4 = 0; c4 < 16; c4++)
        zo[c4] = make_float4(acc[4 * c4], acc[4 * c4 + 1], acc[4 * c4 + 2], acc[4 * c4 + 3]);
}

// ---------------- per-channel sum & sumsq (for BN) ----------------
// requires blockDim (=256) % C == 0 so each thread's channel is fixed
__global__ void __launch_bounds__(256) k_stats(
    const float* __restrict__ z, long long total, int C, float* __restrict__ sums)
{
    __shared__ float sh[256];
    int t = threadIdx.x;
    if (t < 2 * C) sh[t] = 0.f;
    __syncthreads();

    long long stride = (long long)gridDim.x * blockDim.x;
    float s = 0.f, ss = 0.f;
    for (long long i = (long long)blockIdx.x * blockDim.x + t; i < total; i += stride) {
        float v = z[i]; s += v; ss += v * v;
    }
    int c = t % C;
    atomicAdd(&sh[c], s);
    atomicAdd(&sh[C + c], ss);
    __syncthreads();
    if (t < 2 * C) atomicAdd(&sums[t], sh[t]);
}

__global__ void k_bnfin(const float* __restrict__ sums, const float* __restrict__ gamma,
                        const float* __restrict__ beta, float invN, int C,
                        float* __restrict__ bn)
{
    int c = threadIdx.x;
    if (c >= C) return;
    float mu  = sums[c] * invN;
    float var = sums[C + c] * invN - mu * mu;
    float sc  = gamma[c] * rsqrtf(var + 1e-5f);
    bn[c] = sc;
    bn[C + c] = beta[c] - mu * sc;
}

// ---------------- kernel 5: h = gelu(BN(z1)) @ W1b + b1b ----------------
__global__ void __launch_bounds__(128) k_h(
    const float* __restrict__ z1, const float* __restrict__ bn,
    const float* __restrict__ W1b, const float* __restrict__ b1b,
    float* __restrict__ h, int N)
{
    __shared__ __align__(16) float sW[4096];
    __shared__ float sb[64], ssc[64], ssh[64];
    int t = threadIdx.x;
    for (int i = t; i < 4096; i += 128) sW[i] = W1b[i];
    if (t < 64) { sb[t] = b1b[t]; ssc[t] = bn[t]; ssh[t] = bn[64 + t]; }
    __syncthreads();

    int n = blockIdx.x * 128 + t;
    if (n >= N) return;

    const float4* zr = (const float4*)(z1 + (size_t)n * 64);
    float acc[64];
#pragma unroll
    for (int c = 0; c < 64; c++) acc[c] = sb[c];
#pragma unroll 2
    for (int k4 = 0; k4 < 16; k4++) {
        float4 zv = zr[k4];
        float xs[4];
        xs[0] = gelu_(zv.x * ssc[4 * k4 + 0] + ssh[4 * k4 + 0]);
        xs[1] = gelu_(zv.y * ssc[4 * k4 + 1] + ssh[4 * k4 + 1]);
        xs[2] = gelu_(zv.z * ssc[4 * k4 + 2] + ssh[4 * k4 + 2]);
        xs[3] = gelu_(zv.w * ssc[4 * k4 + 3] + ssh[4 * k4 + 3]);
#pragma unroll
        for (int s = 0; s < 4; s++) {
            float x = xs[s];
            const float4* wr = (const float4*)(sW + (4 * k4 + s) * 64);
#pragma unroll
            for (int c4 = 0; c4 < 16; c4++) {
                float4 w = wr[c4];
                acc[4 * c4 + 0] += x * w.x; acc[4 * c4 + 1] += x * w.y;
                acc[4 * c4 + 2] += x * w.z; acc[4 * c4 + 3] += x * w.w;
            }
        }
    }
    float4* ho = (float4*)(h + (size_t)n * 64);
#pragma unroll
    for (int c4 = 0; c4 < 16; c4++)
        ho[c4] = make_float4(acc[4 * c4], acc[4 * c4 + 1], acc[4 * c4 + 2], acc[4 * c4 + 3]);
}

// ---------------- kernel 6: agg2[dst] += h[src]  (16 threads/edge, v4 reds) ----------------
__global__ void __launch_bounds__(256) k_edge2(
    const int* __restrict__ ei, const float* __restrict__ h,
    float* __restrict__ agg2, int E)
{
    unsigned long long t = (unsigned long long)blockIdx.x * 256ull + threadIdx.x;
    int e = (int)(t >> 4);
    int g = (int)(t & 15);
    if (e >= E) return;
    int src = ei[e], dst = ei[E + e];
    float4 v = __ldg((const float4*)(h + (size_t)src * 64) + g);
    red4(agg2 + (size_t)dst * 64 + g * 4, v.x, v.y, v.z, v.w);
}

// ---------------- kernel 7: z2 = ((1+eps2)*h + agg2) @ W2a + b2a ----------------
// 2 threads per node, each 64 of 128 output channels
__global__ void __launch_bounds__(256) k_node2(
    const float* __restrict__ h, const float* __restrict__ agg2,
    const float* __restrict__ W2a, const float* __restrict__ b2a,
    const float* __restrict__ eps2, float* __restrict__ z2, int N)
{
    __shared__ __align__(16) float sW[8200];  // halves split with 8-float pad (bank stagger)
    __shared__ float sb[128];
    int t = threadIdx.x;
    for (int i = t; i < 8192; i += 256) {
        int k = i >> 7, c = i & 127;
        sW[(c >> 6) * 4104 + k * 64 + (c & 63)] = W2a[i];
    }
    if (t < 128) sb[t] = b2a[t];
    __syncthreads();

    int gt = blockIdx.x * 256 + t;
    int n = gt >> 1, half = gt & 1;
    if (n >= N) return;

    float e2 = 1.0f + eps2[0];
    const float4* hr = (const float4*)(h + (size_t)n * 64);
    const float4* ar = (const float4*)(agg2 + (size_t)n * 64);
    float acc[64];
#pragma unroll
    for (int c = 0; c < 64; c++) acc[c] = sb[half * 64 + c];
    const float* sWh = sW + half * 4104;
#pragma unroll 2
    for (int k4 = 0; k4 < 16; k4++) {
        float4 hv = hr[k4]; float4 av = ar[k4];
        float xs[4] = { fmaf(e2, hv.x, av.x), fmaf(e2, hv.y, av.y),
                        fmaf(e2, hv.z, av.z), fmaf(e2, hv.w, av.w) };
#pragma unroll
        for (int s = 0; s < 4; s++) {
            float x = xs[s];
            const float4* wr = (const float4*)(sWh + (4 * k4 + s) * 64);
#pragma unroll
            for (int c4 = 0; c4 < 16; c4++) {
                float4 w = wr[c4];
                acc[4 * c4 + 0] += x * w.x; acc[4 * c4 + 1] += x * w.y;
                acc[4 * c4 + 2] += x * w.z; acc[4 * c4 + 3] += x * w.w;
            }
        }
    }
    float4* zo = (float4*)(z2 + (size_t)n * 128 + half * 64);
#pragma unroll
    for (int c4 = 0; c4 < 16; c4++)
        zo[c4] = make_float4(acc[4 * c4], acc[4 * c4 + 1], acc[4 * c4 + 2], acc[4 * c4 + 3]);
}

// ---------------- kernel 10: h2 = gelu(BN(z2)) @ W2b + b2b ; pooled[batch] += h2 ----------------
// 256 threads handle 128 nodes; gelu'd inputs staged in shared (stride 129: conflict-free)
__global__ void __launch_bounds__(256) k_h2pool(
    const float* __restrict__ z2, const float* __restrict__ bn,
    const float* __restrict__ W2b, const float* __restrict__ b2b,
    const int* __restrict__ batch, float* __restrict__ pooled, int N)
{
    extern __shared__ float smem[];
    float* sW = smem;            // 16392 floats (two 8192 halves + 8 pad)
    float* sx = smem + 16392;    // 128 * 129
    __shared__ float sb[128], sbn[256];

    int t = threadIdx.x;
    for (int i = t; i < 16384; i += 256) {
        int k = i >> 7, c = i & 127;
        sW[(c >> 6) * 8200 + k * 64 + (c & 63)] = W2b[i];
    }
    if (t < 128) sb[t] = b2b[t];
    sbn[t] = bn[t];
    __syncthreads();

    int local = t >> 1, half = t & 1;
    int n = blockIdx.x * 128 + local;
    if (n < N) {
        const float4* zr = (const float4*)(z2 + (size_t)n * 128 + half * 64);
#pragma unroll 4
        for (int k4 = 0; k4 < 16; k4++) {
            float4 zv = zr[k4];
            int k = half * 64 + 4 * k4;
            sx[local * 129 + k + 0] = gelu_(zv.x * sbn[k + 0] + sbn[128 + k + 0]);
            sx[local * 129 + k + 1] = gelu_(zv.y * sbn[k + 1] + sbn[128 + k + 1]);
            sx[local * 129 + k + 2] = gelu_(zv.z * sbn[k + 2] + sbn[128 + k + 2]);
            sx[local * 129 + k + 3] = gelu_(zv.w * sbn[k + 3] + sbn[128 + k + 3]);
        }
    }
    __syncthreads();
    if (n >= N) return;

    float acc[64];
#pragma unroll
    for (int c = 0; c < 64; c++) acc[c] = sb[half * 64 + c];
    const float* sWh = sW + half * 8200;
    const float* xr = sx + local * 129;
#pragma unroll 2
    for (int k = 0; k < 128; k++) {
        float x = xr[k];
        const float4* wr = (const float4*)(sWh + k * 64);
#pragma unroll
        for (int c4 = 0; c4 < 16; c4++) {
            float4 w = wr[c4];
            acc[4 * c4 + 0] += x * w.x; acc[4 * c4 + 1] += x * w.y;
            acc[4 * c4 + 2] += x * w.z; acc[4 * c4 + 3] += x * w.w;
        }
    }
    int b = batch[n];
    float* pp = pooled + (size_t)b * 128 + half * 64;
#pragma unroll
    for (int c4 = 0; c4 < 16; c4++)
        red4(pp + 4 * c4, acc[4 * c4], acc[4 * c4 + 1], acc[4 * c4 + 2], acc[4 * c4 + 3]);
}

// ---------------- kernel 11: out = gelu(pooled @ Wp + bp) ----------------
__global__ void __launch_bounds__(128) k_out(
    const float* __restrict__ pooled, const float* __restrict__ Wp,
    const float* __restrict__ bp, float* __restrict__ out, int B)
{
    int b = blockIdx.x, c = threadIdx.x;
    const float* pr = pooled + (size_t)b * 128;
    float a = bp[c];
#pragma unroll 8
    for (int k = 0; k < 128; k++) a += pr[k] * Wp[k * 128 + c];
    out[(size_t)b * 128 + c] = gelu_(a);
}

// ---------------- launcher ----------------
extern "C" void kernel_launch(void* const* d_in, const int* in_sizes, int n_in,
                              void* d_out, int out_size)
{
    const float* nodes = (const float*)d_in[0];
    const int*   ei    = (const int*)d_in[1];
    const float* ef    = (const float*)d_in[2];
    const int*   batch = (const int*)d_in[3];
    // d_in[4] = B scalar (unused; derived from out_size)
    const float* We1  = (const float*)d_in[5];
    const float* be1  = (const float*)d_in[6];
    const float* We2  = (const float*)d_in[7];
    const float* be2  = (const float*)d_in[8];
    const float* Wego = (const float*)d_in[9];
    const float* W1a  = (const float*)d_in[10];
    const float* b1a  = (const float*)d_in[11];
    const float* g1   = (const float*)d_in[12];
    const float* bta1 = (const float*)d_in[13];
    const float* W1b  = (const float*)d_in[14];
    const float* b1b  = (const float*)d_in[15];
    const float* eps1 = (const float*)d_in[16];
    const float* W2a  = (const float*)d_in[17];
    const float* b2a  = (const float*)d_in[18];
    const float* g2   = (const float*)d_in[19];
    const float* bta2 = (const float*)d_in[20];
    const float* W2b  = (const float*)d_in[21];
    const float* b2b  = (const float*)d_in[22];
    const float* eps2 = (const float*)d_in[23];
    const float* Wp   = (const float*)d_in[24];
    const float* bp   = (const float*)d_in[25];

    int N = in_sizes[0] / 5;
    int E = in_sizes[1] / 2;
    int B = out_size / 128;

    float *agg1, *z1, *h, *agg2, *z2, *stats, *bn1, *bn2, *pooled;
    cudaGetSymbolAddress((void**)&agg1,   g_agg1);
    cudaGetSymbolAddress((void**)&z1,     g_z1);
    cudaGetSymbolAddress((void**)&h,      g_h);
    cudaGetSymbolAddress((void**)&agg2,   g_agg2);
    cudaGetSymbolAddress((void**)&z2,     g_z2);
    cudaGetSymbolAddress((void**)&stats,  g_stats);
    cudaGetSymbolAddress((void**)&bn1,    g_bn1);
    cudaGetSymbolAddress((void**)&bn2,    g_bn2);
    cudaGetSymbolAddress((void**)&pooled, g_pooled);

    cudaMemsetAsync(agg1,   0, (size_t)N * 24 * sizeof(float), 0);
    cudaMemsetAsync(agg2,   0, (size_t)N * 64 * sizeof(float), 0);
    cudaMemsetAsync(stats,  0, 384 * sizeof(float), 0);
    cudaMemsetAsync(pooled, 0, (size_t)B * 128 * sizeof(float), 0);

    float invN = 1.0f / (float)N;

    k_edge1<<<(E + 255) / 256, 256>>>(ei, ef, nodes, We1, be1, We2, be2, agg1, E);
    k_node1<<<(N + 127) / 128, 128>>>(nodes, agg1, Wego, W1a, b1a, eps1, z1, N);
    k_stats<<<2048, 256>>>(z1, (long long)N * 64, 64, stats);
    k_bnfin<<<1, 64>>>(stats, g1, bta1, invN, 64, bn1);
    k_h<<<(N + 127) / 128, 128>>>(z1, bn1, W1b, b1b, h, N);

    long long t2 = (long long)E * 16;
    k_edge2<<<(unsigned int)((t2 + 255) / 256), 256>>>(ei, h, agg2, E);

    k_node2<<<(2 * N + 255) / 256, 256>>>(h, agg2, W2a, b2a, eps2, z2, N);
    k_stats<<<2048, 256>>>(z2, (long long)N * 128, 128, stats + 128);
    k_bnfin<<<1, 128>>>(stats + 128, g2, bta2, invN, 128, bn2);

    int smem10 = (16392 + 128 * 129) * sizeof(float);
    cudaFuncSetAttribute(k_h2pool, cudaFuncAttributeMaxDynamicSharedMemorySize, smem10);
    k_h2pool<<<(N + 127) / 128, 256, smem10>>>(z2, bn2, W2b, b2b, batch, pooled, N);

    k_out<<<B, 128>>>(pooled, Wp, bp, (float*)d_out, B);
}

// round 3
// speedup vs baseline: 1.5767x; 1.5767x over previous
#include <cuda_runtime.h>
#include <math.h>

#define MAXN 200000
#define MAXE 3200000

typedef unsigned long long u64;

// ---------------- scratch (device globals: no allocation allowed) ----------------
__device__ int   g_rowptr[MAXN + 1];
__device__ int   g_cursor[MAXN];
__device__ int   g_bsum[128];
__device__ int   g_srcp[MAXE];
__device__ __align__(16) float g_msg[(size_t)MAXE * 16];
__device__ __align__(16) float g_u[(size_t)MAXN * 24];
__device__ __align__(16) float g_z1[(size_t)MAXN * 64];
__device__ __align__(16) float g_h[(size_t)MAXN * 64];
__device__ __align__(16) float g_u2[(size_t)MAXN * 64];
__device__ __align__(16) float g_z2[(size_t)MAXN * 128];
__device__ float g_stats[384];
__device__ float g_bn1[128];
__device__ float g_bn2[256];
__device__ __align__(16) float g_pooled[64 * 128];

__device__ __forceinline__ float gelu_(float x) {
    return 0.5f * x * (1.0f + erff(x * 0.7071067811865476f));
}
__device__ __forceinline__ void red4(float* p, float a, float b, float c, float d) {
    asm volatile("red.global.add.v4.f32 [%0], {%1,%2,%3,%4};"
                 :: "l"(p), "f"(a), "f"(b), "f"(c), "f"(d) : "memory");
}
__device__ __forceinline__ u64 pk2(float x, float y) {
    u64 r; asm("mov.b64 %0,{%1,%2};" : "=l"(r) : "f"(x), "f"(y)); return r;
}
__device__ __forceinline__ void fma2(u64& d, u64 a, u64 b) {
    asm("fma.rn.f32x2 %0,%1,%2,%0;" : "+l"(d) : "l"(a), "l"(b));
}
__device__ __forceinline__ float2 up2(u64 v) {
    float2 r; asm("mov.b64 {%0,%1},%2;" : "=f"(r.x), "=f"(r.y) : "l"(v)); return r;
}

// ---------------- CSR build ----------------
__global__ void __launch_bounds__(256) k_hist(const int* __restrict__ ei,
                                              int* __restrict__ deg, int E)
{
    int e = blockIdx.x * 256 + threadIdx.x;
    if (e < E) atomicAdd(&deg[ei[E + e]], 1);
}

__global__ void __launch_bounds__(256) k_scan_part(int* __restrict__ rowptr,
                                                   int* __restrict__ bsum, int N)
{
    __shared__ int sh[256];
    int t = threadIdx.x;
    int base = blockIdx.x * 2048 + t * 8;
    int loc[8]; int s = 0;
#pragma unroll
    for (int j = 0; j < 8; j++) { int i = base + j; loc[j] = (i < N) ? rowptr[i] : 0; s += loc[j]; }
    sh[t] = s; __syncthreads();
    for (int off = 1; off < 256; off <<= 1) {
        int v = (t >= off) ? sh[t - off] : 0;
        __syncthreads();
        sh[t] += v;
        __syncthreads();
    }
    int excl = sh[t] - s;
    if (t == 255) bsum[blockIdx.x] = sh[255];
#pragma unroll
    for (int j = 0; j < 8; j++) {
        int i = base + j;
        if (i < N) { int v = loc[j]; rowptr[i] = excl; excl += v; }
    }
}

__global__ void k_scan_top(int* __restrict__ bsum, int nb)
{
    if (threadIdx.x == 0) {
        int run = 0;
        for (int i = 0; i < nb; i++) { int v = bsum[i]; bsum[i] = run; run += v; }
    }
}

__global__ void __launch_bounds__(256) k_scan_add(int* __restrict__ rowptr,
                                                  int* __restrict__ cursor,
                                                  const int* __restrict__ bsum,
                                                  int N, int E)
{
    int i = blockIdx.x * 256 + threadIdx.x;
    if (i < N) {
        int v = rowptr[i] + bsum[i >> 11];
        rowptr[i] = v; cursor[i] = v;
    }
    if (i == 0) rowptr[N] = E;
}

// ---------------- edge MLP -> permuted msg (grouped by dst) ----------------
__global__ void __launch_bounds__(256) k_edge1(
    const int* __restrict__ ei, const float* __restrict__ ef,
    const float* __restrict__ We1, const float* __restrict__ be1,
    const float* __restrict__ We2, const float* __restrict__ be2,
    int* __restrict__ cursor, float* __restrict__ msg, int* __restrict__ srcp, int E)
{
    __shared__ float sWe1[48], sbe1[16], sbe2[16];
    __shared__ __align__(8) float sWe2[256];
    int t = threadIdx.x;
    if (t < 48)  sWe1[t] = We1[t];
    if (t < 16)  sbe1[t] = be1[t];
    if (t < 256) sWe2[t] = We2[t];
    if (t >= 48 && t < 64) sbe2[t - 48] = be2[t - 48];
    __syncthreads();

    int e = blockIdx.x * 256 + t;
    if (e >= E) return;

    float f0 = ef[3 * e], f1 = ef[3 * e + 1], f2 = ef[3 * e + 2];
    float emb[16];
#pragma unroll
    for (int j = 0; j < 16; j++) {
        float v = sbe1[j] + f0 * sWe1[j] + f1 * sWe1[16 + j] + f2 * sWe1[32 + j];
        emb[j] = gelu_(v);
    }
    u64 acc[8];
#pragma unroll
    for (int i = 0; i < 8; i++) acc[i] = pk2(sbe2[2 * i], sbe2[2 * i + 1]);
#pragma unroll
    for (int k = 0; k < 16; k++) {
        u64 ek = pk2(emb[k], emb[k]);
        const u64* wp = (const u64*)(sWe2 + k * 16);
#pragma unroll
        for (int i = 0; i < 8; i++) fma2(acc[i], ek, wp[i]);
    }
    int src = ei[e], dst = ei[E + e];
    int pos = atomicAdd(&cursor[dst], 1);
    float4* mp = (float4*)(msg + (size_t)pos * 16);
#pragma unroll
    for (int i4 = 0; i4 < 4; i4++) {
        float2 a = up2(acc[2 * i4]), b = up2(acc[2 * i4 + 1]);
        mp[i4] = make_float4(a.x, a.y, b.x, b.y);
    }
    srcp[pos] = src;
}

// ---------------- agg1 + ego -> u[N][24] (21 used) ----------------
__global__ void __launch_bounds__(256) k_agg1u(
    const int* __restrict__ rowptr, const int* __restrict__ srcp,
    const float* __restrict__ msg, const float* __restrict__ nodes,
    const float* __restrict__ Wego, const float* __restrict__ eps1,
    float* __restrict__ u, int N)
{
    __shared__ float sWe[105];
    int tid = threadIdx.x;
    if (tid < 105) sWe[tid] = Wego[tid];
    __syncthreads();

    int wid = blockIdx.x * 8 + (tid >> 5);
    if (wid >= N) return;
    int c = tid & 31;
    int beg = rowptr[wid], end = rowptr[wid + 1];
    float s = 0.f;
    if (c < 21) {
#pragma unroll 4
        for (int e = beg; e < end; e++) {
            float v;
            if (c < 5) v = __ldg(nodes + (size_t)srcp[e] * 5 + c);
            else       v = msg[(size_t)e * 16 + (c - 5)];
            s += v;
        }
        const float* nr = nodes + (size_t)wid * 5;
        float x0 = nr[0], x1 = nr[1], x2 = nr[2], x3 = nr[3], x4 = nr[4];
        float ego = x0 * sWe[c] + x1 * sWe[21 + c] + x2 * sWe[42 + c]
                  + x3 * sWe[63 + c] + x4 * sWe[84 + c];
        u[(size_t)wid * 24 + c] = fmaf(1.f + eps1[0], ego, s);
    }
}

// ---------------- agg2 + (1+eps2)h -> u2[N][64] ----------------
__global__ void __launch_bounds__(256) k_agg2h2(
    const int* __restrict__ rowptr, const int* __restrict__ srcp,
    const float* __restrict__ h, const float* __restrict__ eps2,
    float* __restrict__ u2, int N)
{
    int wid = blockIdx.x * 8 + (threadIdx.x >> 5);
    if (wid >= N) return;
    int l = threadIdx.x & 31;
    int beg = rowptr[wid], end = rowptr[wid + 1];
    float a0 = 0.f, a1 = 0.f;
    int e = beg;
    for (; e + 1 < end; e += 2) {
        const float* p0 = h + (size_t)srcp[e] * 64;
        const float* p1 = h + (size_t)srcp[e + 1] * 64;
        a0 += p0[l] + p1[l];
        a1 += p0[32 + l] + p1[32 + l];
    }
    if (e < end) {
        const float* p = h + (size_t)srcp[e] * 64;
        a0 += p[l]; a1 += p[32 + l];
    }
    float e2 = 1.f + eps2[0];
    const float* hn = h + (size_t)wid * 64;
    u2[(size_t)wid * 64 + l]      = fmaf(e2, hn[l], a0);
    u2[(size_t)wid * 64 + 32 + l] = fmaf(e2, hn[32 + l], a1);
}

// ---------------- BN stats ----------------
__global__ void __launch_bounds__(256) k_stats(
    const float* __restrict__ z, long long total, int C, float* __restrict__ sums)
{
    __shared__ float sh[256];
    int t = threadIdx.x;
    if (t < 2 * C) sh[t] = 0.f;
    __syncthreads();
    long long stride = (long long)gridDim.x * blockDim.x;
    float s = 0.f, ss = 0.f;
    for (long long i = (long long)blockIdx.x * blockDim.x + t; i < total; i += stride) {
        float v = z[i]; s += v; ss += v * v;
    }
    int c = t % C;
    atomicAdd(&sh[c], s);
    atomicAdd(&sh[C + c], ss);
    __syncthreads();
    if (t < 2 * C) atomicAdd(&sums[t], sh[t]);
}

__global__ void k_bnfin(const float* __restrict__ sums, const float* __restrict__ gamma,
                        const float* __restrict__ beta, float invN, int C,
                        float* __restrict__ bn)
{
    int c = threadIdx.x;
    if (c >= C) return;
    float mu  = sums[c] * invN;
    float var = sums[C + c] * invN - mu * mu;
    float sc  = gamma[c] * rsqrtf(var + 1e-5f);
    bn[c] = sc;
    bn[C + c] = beta[c] - mu * sc;
}

// ---------------- tiled GEMM: 128 nodes/block, thread = 4 nodes x 16 ch ----------------
// MIN: 0 plain X, 1 gelu(bn(X)).  MOUT: 0 store Z, 1 pooled reduction (C must be 128).
template<int K, int KP, int C, int MIN, int MOUT>
__global__ void __launch_bounds__((C / 16) * 32)
k_gemm(const float* __restrict__ X, const float* __restrict__ W,
       const float* __restrict__ bias, const float* __restrict__ bn,
       float* __restrict__ Z, const int* __restrict__ batch,
       float* __restrict__ pooled, int N)
{
    extern __shared__ __align__(16) float sm[];
    float* sx = sm;                 // KP * 132
    float* sw = sm + KP * 132;      // K * C
    float* sb = sw + K * C;         // C
    const int T = (C / 16) * 32;
    int tid = threadIdx.x;
    int n0 = blockIdx.x * 128;

    for (int i = tid; i < K * C / 4; i += T)
        ((float4*)sw)[i] = ((const float4*)W)[i];
    if (tid < C) sb[tid] = bias[tid];

    for (int idx = tid; idx < 128 * (KP / 4); idx += T) {
        int n = idx & 127, j = idx >> 7;
        float4 v = make_float4(0.f, 0.f, 0.f, 0.f);
        if (n0 + n < N) v = ((const float4*)(X + (size_t)(n0 + n) * KP))[j];
        if (MIN == 1) {
            int k = 4 * j;
            v.x = gelu_(fmaf(v.x, bn[k + 0], bn[K + k + 0]));
            v.y = gelu_(fmaf(v.y, bn[k + 1], bn[K + k + 1]));
            v.z = gelu_(fmaf(v.z, bn[k + 2], bn[K + k + 2]));
            v.w = gelu_(fmaf(v.w, bn[k + 3], bn[K + k + 3]));
        }
        sx[(4 * j + 0) * 132 + n] = v.x;
        sx[(4 * j + 1) * 132 + n] = v.y;
        sx[(4 * j + 2) * 132 + n] = v.z;
        sx[(4 * j + 3) * 132 + n] = v.w;
    }
    __syncthreads();

    int w = tid >> 5, l = tid & 31;
    u64 acc[32];
#pragma unroll
    for (int i = 0; i < 32; i++) acc[i] = 0ull;

    const float* xbase = sx + 4 * l;
    const float* wbase = sw + 16 * w;
#pragma unroll 2
    for (int k = 0; k < K; k++) {
        float4 xv = *(const float4*)(xbase + k * 132);
        const u64* wp = (const u64*)(wbase + k * C);
        u64 wv[8];
#pragma unroll
        for (int i = 0; i < 8; i++) wv[i] = wp[i];
        u64 xp[4] = { pk2(xv.x, xv.x), pk2(xv.y, xv.y), pk2(xv.z, xv.z), pk2(xv.w, xv.w) };
#pragma unroll
        for (int nn = 0; nn < 4; nn++)
#pragma unroll
            for (int i = 0; i < 8; i++)
                fma2(acc[nn * 8 + i], xp[nn], wv[i]);
    }

    float bb[16];
#pragma unroll
    for (int i = 0; i < 16; i++) bb[i] = sb[16 * w + i];

    if (MOUT == 0) {
#pragma unroll
        for (int nn = 0; nn < 4; nn++) {
            int n = n0 + 4 * l + nn;
            if (n < N) {
                float4* zp = (float4*)(Z + (size_t)n * C + 16 * w);
#pragma unroll
                for (int i4 = 0; i4 < 4; i4++) {
                    float2 p0 = up2(acc[nn * 8 + 2 * i4]);
                    float2 p1 = up2(acc[nn * 8 + 2 * i4 + 1]);
                    zp[i4] = make_float4(p0.x + bb[4 * i4 + 0], p0.y + bb[4 * i4 + 1],
                                         p1.x + bb[4 * i4 + 2], p1.y + bb[4 * i4 + 3]);
                }
            }
        }
    } else {
        float run[16];
        int curb = -1;
#pragma unroll
        for (int nn = 0; nn < 4; nn++) {
            int n = n0 + 4 * l + nn;
            if (n < N) {
                int b = batch[n];
                float vals[16];
#pragma unroll
                for (int i = 0; i < 8; i++) {
                    float2 p = up2(acc[nn * 8 + i]);
                    vals[2 * i]     = p.x + bb[2 * i];
                    vals[2 * i + 1] = p.y + bb[2 * i + 1];
                }
                if (b != curb) {
                    if (curb >= 0) {
                        float* pp = pooled + (size_t)curb * 128 + 16 * w;
                        red4(pp,      run[0],  run[1],  run[2],  run[3]);
                        red4(pp + 4,  run[4],  run[5],  run[6],  run[7]);
                        red4(pp + 8,  run[8],  run[9],  run[10], run[11]);
                        red4(pp + 12, run[12], run[13], run[14], run[15]);
                    }
                    curb = b;
#pragma unroll
                    for (int i = 0; i < 16; i++) run[i] = vals[i];
                } else {
#pragma unroll
                    for (int i = 0; i < 16; i++) run[i] += vals[i];
                }
            }
        }
        if (curb >= 0) {
            float* pp = pooled + (size_t)curb * 128 + 16 * w;
            red4(pp,      run[0],  run[1],  run[2],  run[3]);
            red4(pp + 4,  run[4],  run[5],  run[6],  run[7]);
            red4(pp + 8,  run[8],  run[9],  run[10], run[11]);
            red4(pp + 12, run[12], run[13], run[14], run[15]);
        }
    }
}

// ---------------- out = gelu(pooled @ Wp + bp) ----------------
__global__ void __launch_bounds__(128) k_out(
    const float* __restrict__ pooled, const float* __restrict__ Wp,
    const float* __restrict__ bp, float* __restrict__ out, int B)
{
    int b = blockIdx.x, c = threadIdx.x;
    const float* pr = pooled + (size_t)b * 128;
    float a = bp[c];
#pragma unroll 8
    for (int k = 0; k < 128; k++) a += pr[k] * Wp[k * 128 + c];
    out[(size_t)b * 128 + c] = gelu_(a);
}

// ---------------- launcher ----------------
extern "C" void kernel_launch(void* const* d_in, const int* in_sizes, int n_in,
                              void* d_out, int out_size)
{
    const float* nodes = (const float*)d_in[0];
    const int*   ei    = (const int*)d_in[1];
    const float* ef    = (const float*)d_in[2];
    const int*   batch = (const int*)d_in[3];
    const float* We1  = (const float*)d_in[5];
    const float* be1  = (const float*)d_in[6];
    const float* We2  = (const float*)d_in[7];
    const float* be2  = (const float*)d_in[8];
    const float* Wego = (const float*)d_in[9];
    const float* W1a  = (const float*)d_in[10];
    const float* b1a  = (const float*)d_in[11];
    const float* g1   = (const float*)d_in[12];
    const float* bta1 = (const float*)d_in[13];
    const float* W1b  = (const float*)d_in[14];
    const float* b1b  = (const float*)d_in[15];
    const float* eps1 = (const float*)d_in[16];
    const float* W2a  = (const float*)d_in[17];
    const float* b2a  = (const float*)d_in[18];
    const float* g2   = (const float*)d_in[19];
    const float* bta2 = (const float*)d_in[20];
    const float* W2b  = (const float*)d_in[21];
    const float* b2b  = (const float*)d_in[22];
    const float* eps2 = (const float*)d_in[23];
    const float* Wp   = (const float*)d_in[24];
    const float* bp   = (const float*)d_in[25];

    int N = in_sizes[0] / 5;
    int E = in_sizes[1] / 2;
    int B = out_size / 128;

    int *rowptr, *cursor, *bsum, *srcp;
    float *msg, *u, *z1, *h, *u2, *z2, *stats, *bn1, *bn2, *pooled;
    cudaGetSymbolAddress((void**)&rowptr, g_rowptr);
    cudaGetSymbolAddress((void**)&cursor, g_cursor);
    cudaGetSymbolAddress((void**)&bsum,   g_bsum);
    cudaGetSymbolAddress((void**)&srcp,   g_srcp);
    cudaGetSymbolAddress((void**)&msg,    g_msg);
    cudaGetSymbolAddress((void**)&u,      g_u);
    cudaGetSymbolAddress((void**)&z1,     g_z1);
    cudaGetSymbolAddress((void**)&h,      g_h);
    cudaGetSymbolAddress((void**)&u2,     g_u2);
    cudaGetSymbolAddress((void**)&z2,     g_z2);
    cudaGetSymbolAddress((void**)&stats,  g_stats);
    cudaGetSymbolAddress((void**)&bn1,    g_bn1);
    cudaGetSymbolAddress((void**)&bn2,    g_bn2);
    cudaGetSymbolAddress((void**)&pooled, g_pooled);

    cudaMemsetAsync(rowptr, 0, (size_t)(N + 1) * sizeof(int), 0);
    cudaMemsetAsync(stats,  0, 384 * sizeof(float), 0);
    cudaMemsetAsync(pooled, 0, (size_t)B * 128 * sizeof(float), 0);

    float invN = 1.0f / (float)N;
    int nScanBlocks = (N + 2047) / 2048;

    // CSR build
    k_hist<<<(E + 255) / 256, 256>>>(ei, rowptr, E);
    k_scan_part<<<nScanBlocks, 256>>>(rowptr, bsum, N);
    k_scan_top<<<1, 32>>>(bsum, nScanBlocks);
    k_scan_add<<<(N + 255) / 256, 256>>>(rowptr, cursor, bsum, N, E);

    // layer 1
    k_edge1<<<(E + 255) / 256, 256>>>(ei, ef, We1, be1, We2, be2, cursor, msg, srcp, E);
    k_agg1u<<<(N + 7) / 8, 256>>>(rowptr, srcp, msg, nodes, Wego, eps1, u, N);

    const int SM1 = (24 * 132 + 21 * 64 + 64) * 4;
    const int SMH = (64 * 132 + 64 * 64 + 64) * 4;
    const int SM2 = (64 * 132 + 64 * 128 + 128) * 4;
    const int SM3 = (128 * 132 + 128 * 128 + 128) * 4;
    int nTiles = (N + 127) / 128;

    k_gemm<21, 24, 64, 0, 0><<<nTiles, 128, SM1>>>(u, W1a, b1a, nullptr, z1, nullptr, nullptr, N);
    k_stats<<<2048, 256>>>(z1, (long long)N * 64, 64, stats);
    k_bnfin<<<1, 64>>>(stats, g1, bta1, invN, 64, bn1);

    cudaFuncSetAttribute((const void*)k_gemm<64, 64, 64, 1, 0>,
                         cudaFuncAttributeMaxDynamicSharedMemorySize, SMH);
    k_gemm<64, 64, 64, 1, 0><<<nTiles, 128, SMH>>>(z1, W1b, b1b, bn1, h, nullptr, nullptr, N);

    // layer 2
    k_agg2h2<<<(N + 7) / 8, 256>>>(rowptr, srcp, h, eps2, u2, N);

    cudaFuncSetAttribute((const void*)k_gemm<64, 64, 128, 0, 0>,
                         cudaFuncAttributeMaxDynamicSharedMemorySize, SM2);
    k_gemm<64, 64, 128, 0, 0><<<nTiles, 256, SM2>>>(u2, W2a, b2a, nullptr, z2, nullptr, nullptr, N);
    k_stats<<<2048, 256>>>(z2, (long long)N * 128, 128, stats + 128);
    k_bnfin<<<1, 128>>>(stats + 128, g2, bta2, invN, 128, bn2);

    cudaFuncSetAttribute((const void*)k_gemm<128, 128, 128, 1, 1>,
                         cudaFuncAttributeMaxDynamicSharedMemorySize, SM3);
    k_gemm<128, 128, 128, 1, 1><<<nTiles, 256, SM3>>>(z2, W2b, b2b, bn2, nullptr, batch, pooled, N);

    k_out<<<B, 128>>>(pooled, Wp, bp, (float*)d_out, B);
}